// round 14
// baseline (speedup 1.0000x reference)
#include <cuda_runtime.h>

#define TT  1024
#define NB  128
#define VV  35
#define HH  512
#define VS  128
#define KSZ 128
#define G1  2048
#define ML  250
#define NBLK 128

typedef unsigned long long ull;

__device__ float d_inpc[NB*G1];
__device__ float d_toktab[VV*G1];
__device__ float d_h1[2][NB*HH];
__device__ float d_c1[NB*HH];
__device__ float d_h2[2][NB*KSZ];
__device__ float d_c2[NB*KSZ];
__device__ int   d_tok[NB];
__device__ unsigned d_barcnt, d_bargen;
__device__ float  d_W1t[32*512*64];
__device__ float4 d_W2d[32*640*8];
__device__ int    d_srt[NB];
__device__ int    d_half[NB];
__device__ float  d_pm[NB*2], d_ps[NB*2];
__device__ float  d_pctx[NB*2*VS];

__device__ __forceinline__ ull pack2(float x) {
    unsigned r = __float_as_uint(x); ull d;
    asm("mov.b64 %0, {%1, %2};" : "=l"(d) : "r"(r), "r"(r));
    return d;
}
__device__ __forceinline__ void ffma2(ull& c, ull a, ull b) {
    asm("fma.rn.f32x2 %0, %1, %2, %0;" : "+l"(c) : "l"(a), "l"(b));
}
__device__ __forceinline__ float2 unpack2(ull v) {
    unsigned lo, hi;
    asm("mov.b64 {%0, %1}, %2;" : "=r"(lo), "=r"(hi) : "l"(v));
    return make_float2(__uint_as_float(lo), __uint_as_float(hi));
}
__device__ __forceinline__ float sigf(float x) { return 1.0f / (1.0f + expf(-x)); }

__device__ __forceinline__ void grid_bar() {
    __threadfence();
    __syncthreads();
    if (threadIdx.x == 0) {
        volatile unsigned* genp = &d_bargen;
        unsigned gen = *genp;
        if (atomicAdd(&d_barcnt, 1u) == NBLK - 1) {
            d_barcnt = 0; __threadfence(); *genp = gen + 1;
        } else { while (*genp == gen) { } }
        __threadfence();
    }
    __syncthreads();
}

__global__ void __launch_bounds__(256) k_pre(const float* __restrict__ val,
        const float* __restrict__ emb, const float* __restrict__ Wih1,
        const float* __restrict__ bih1, const float* __restrict__ bhh1,
        const float* __restrict__ Whh1, const float* __restrict__ Wih2,
        const float* __restrict__ Whh2, const int* __restrict__ lens) {
    __shared__ float vp[2][VS];
    __shared__ float vm[VS];
    __shared__ float e[HH];
    int n = blockIdx.x, tid = threadIdx.x;
    {
        int ch = tid & 127, hp = tid >> 7;
        const float* p = val + (size_t)hp*NB*VS + n*VS + ch;
        float s = 0.f;
        #pragma unroll 8
        for (int t = 0; t < TT/2; t++) s += p[(size_t)t*2*NB*VS];
        vp[hp][ch] = s;
    }
    __syncthreads();
    if (tid < VS) vm[tid] = (vp[0][tid] + vp[1][tid]) * (1.0f/TT);
    __syncthreads();
    for (int j = tid; j < G1; j += 256) {
        const float4* w4 = (const float4*)(Wih1 + (size_t)j*(HH+VS) + HH);
        float s = 0.f;
        #pragma unroll 8
        for (int v = 0; v < VS/4; v++) {
            float4 w = w4[v];
            s += w.x*vm[4*v] + w.y*vm[4*v+1] + w.z*vm[4*v+2] + w.w*vm[4*v+3];
        }
        d_inpc[n*G1 + j] = s + bih1[j] + bhh1[j];
    }
    if (n < VV) {
        for (int k = tid; k < HH; k += 256) e[k] = emb[n*HH + k];
        __syncthreads();
        for (int j = tid; j < G1; j += 256) {
            const float4* w4 = (const float4*)(Wih1 + (size_t)j*(HH+VS));
            float s = 0.f;
            #pragma unroll 8
            for (int k = 0; k < HH/4; k++) {
                float4 w = w4[k];
                s += w.x*e[4*k] + w.y*e[4*k+1] + w.z*e[4*k+2] + w.w*e[4*k+3];
            }
            d_toktab[n*G1 + j] = s;
        }
    }
    int mt = n & 31, kq = n >> 5;
    for (int idx = tid; idx < 128*64; idx += 256) {
        int kk = kq*128 + (idx >> 6), c = idx & 63;
        int r = (c >> 4)*HH + mt*16 + (c & 15);
        d_W1t[((size_t)mt*512 + kk)*64 + c] = Whh1[(size_t)r*HH + kk];
    }
    for (int idx = tid; idx < 160*8; idx += 256) {
        int kk = kq*160 + (idx >> 3), c2 = idx & 7;
        int j0 = 2*c2, j1 = j0 + 1;
        int r0 = (j0 >> 2)*KSZ + mt*4 + (j0 & 3);
        int r1 = (j1 >> 2)*KSZ + mt*4 + (j1 & 3);
        float w0 = (kk < 512) ? Wih2[(size_t)r0*HH + kk] : Whh2[(size_t)r0*KSZ + kk - 512];
        float w1 = (kk < 512) ? Wih2[(size_t)r1*HH + kk] : Whh2[(size_t)r1*KSZ + kk - 512];
        d_W2d[((size_t)mt*640 + kk)*8 + c2] = make_float4(w0, w0, w1, w1);
    }
    for (int i = tid; i < HH; i += 256) { d_h1[0][n*HH+i] = 0.f; d_c1[n*HH+i] = 0.f; }
    if (tid < KSZ) { d_h2[0][n*KSZ+tid] = 0.f; d_c2[n*KSZ+tid] = 0.f; }
    if (tid == 0) {
        d_tok[n] = 0;
        int L = lens[n];
        int h = (((L + 1) >> 1) + 15) & ~15;
        d_half[n] = (h > L) ? L : h;
    }
    if (n == 0 && tid == 0) {
        int ord[NB];
        for (int i = 0; i < NB; i++) ord[i] = i;
        for (int i = 0; i < NB-1; i++) {
            int bi = i;
            for (int j = i+1; j < NB; j++)
                if (lens[ord[j]] > lens[ord[bi]]) bi = j;
            int tmp = ord[i]; ord[i] = ord[bi]; ord[bi] = tmp;
        }
        for (int i = 0; i < NB; i++) d_srt[i] = ord[i];
    }
}

struct SMem {
    float Ws[512][64];                        // persistent W1 tile (128 KB)
    union {
        float As1[512][34];
        float gt1[8][64][33];
        float As2[640][34];
        struct { float gt[16][16][33]; float rs[16][33]; } l2b;
        struct { float h2s[KSZ]; float ev[528]; float cpart[32][VS]; float ctxs[VS];
                 float preds[VV]; float red[32], red2[32]; float cmb[4]; } at;
    } u;
};

__device__ void attn_part(SMem* sm, const float* __restrict__ key,
        const float* __restrict__ val, const float* __restrict__ h2row,
        int n, int ci, int t0, int tl) {
    const int tid = threadIdx.x, lane = tid & 31, wid = tid >> 5;  // 32 warps
    float* ev = sm->u.at.ev;
    __syncthreads();
    if (tid < KSZ) sm->u.at.h2s[tid] = __ldcg(&h2row[tid]);
    __syncthreads();
    const float* krow = key + (size_t)t0*(NB*KSZ) + (size_t)n*KSZ + lane*4;
    const float* vrow = val + (size_t)t0*(NB*VS)  + (size_t)n*VS  + lane*4;
    float4 hv = *(const float4*)&sm->u.at.h2s[lane*4];
    float wmax = -3.0e38f;
    int t = wid;
    for (; t + 96 < tl; t += 128) {
        float4 k0 = *(const float4*)(krow + (size_t)(t     )*(NB*KSZ));
        float4 k1 = *(const float4*)(krow + (size_t)(t + 32)*(NB*KSZ));
        float4 k2 = *(const float4*)(krow + (size_t)(t + 64)*(NB*KSZ));
        float4 k3 = *(const float4*)(krow + (size_t)(t + 96)*(NB*KSZ));
        float s0 = k0.x*hv.x + k0.y*hv.y + k0.z*hv.z + k0.w*hv.w;
        float s1 = k1.x*hv.x + k1.y*hv.y + k1.z*hv.z + k1.w*hv.w;
        float s2 = k2.x*hv.x + k2.y*hv.y + k2.z*hv.z + k2.w*hv.w;
        float s3 = k3.x*hv.x + k3.y*hv.y + k3.z*hv.z + k3.w*hv.w;
        #pragma unroll
        for (int sh = 16; sh; sh >>= 1) {
            s0 += __shfl_xor_sync(~0u, s0, sh); s1 += __shfl_xor_sync(~0u, s1, sh);
            s2 += __shfl_xor_sync(~0u, s2, sh); s3 += __shfl_xor_sync(~0u, s3, sh);
        }
        if (lane == 0) { ev[t]=s0; ev[t+32]=s1; ev[t+64]=s2; ev[t+96]=s3; }
        wmax = fmaxf(wmax, fmaxf(fmaxf(s0,s1), fmaxf(s2,s3)));
    }
    for (; t < tl; t += 32) {
        float4 k0 = *(const float4*)(krow + (size_t)t*(NB*KSZ));
        float s0 = k0.x*hv.x + k0.y*hv.y + k0.z*hv.z + k0.w*hv.w;
        #pragma unroll
        for (int sh = 16; sh; sh >>= 1) s0 += __shfl_xor_sync(~0u, s0, sh);
        if (lane == 0) ev[t] = s0;
        wmax = fmaxf(wmax, s0);
    }
    if (lane == 0) sm->u.at.red[wid] = wmax;
    __syncthreads();
    float m = sm->u.at.red[0];
    #pragma unroll
    for (int w = 1; w < 32; w++) m = fmaxf(m, sm->u.at.red[w]);
    float psum = 0.f;
    if (tid < tl) { float w = expf(ev[tid] - m); ev[tid] = w; psum += w; }
    #pragma unroll
    for (int sh = 16; sh; sh >>= 1) psum += __shfl_xor_sync(~0u, psum, sh);
    if (lane == 0) sm->u.at.red2[wid] = psum;
    __syncthreads();
    float4 a0 = {0,0,0,0}, a1 = {0,0,0,0};
    t = wid;
    for (; t + 32 < tl; t += 64) {
        float e0 = ev[t], e1 = ev[t+32];
        float4 v0 = *(const float4*)(vrow + (size_t)(t     )*(NB*VS));
        float4 v1 = *(const float4*)(vrow + (size_t)(t + 32)*(NB*VS));
        a0.x += e0*v0.x; a0.y += e0*v0.y; a0.z += e0*v0.z; a0.w += e0*v0.w;
        a1.x += e1*v1.x; a1.y += e1*v1.y; a1.z += e1*v1.z; a1.w += e1*v1.w;
    }
    for (; t < tl; t += 32) {
        float e0 = ev[t];
        float4 v0 = *(const float4*)(vrow + (size_t)t*(NB*VS));
        a0.x += e0*v0.x; a0.y += e0*v0.y; a0.z += e0*v0.z; a0.w += e0*v0.w;
    }
    a0.x += a1.x; a0.y += a1.y; a0.z += a1.z; a0.w += a1.w;
    *(float4*)&sm->u.at.cpart[wid][lane*4] = a0;
    __syncthreads();
    if (tid < VS) {
        float s = 0.f;
        #pragma unroll
        for (int w = 0; w < 32; w++) s += sm->u.at.cpart[w][tid];
        d_pctx[((size_t)n*2 + ci)*VS + tid] = s;
    }
    if (tid == 0) {
        float st = 0.f;
        #pragma unroll
        for (int w = 0; w < 32; w++) st += sm->u.at.red2[w];
        d_pm[n*2 + ci] = m;
        d_ps[n*2 + ci] = st;
    }
}

__global__ void __launch_bounds__(1024, 1) k_decode(
    const float* __restrict__ key, const float* __restrict__ val,
    const int* __restrict__ lens,
    const float* __restrict__ bih2, const float* __restrict__ bhh2,
    const float* __restrict__ Wout, const float* __restrict__ bout,
    float* __restrict__ out)
{
    extern __shared__ __align__(16) char smraw[];
    SMem* sm = (SMem*)smraw;
    const int bid = blockIdx.x, tid = threadIdx.x;
    const int lane = tid & 31, wid = tid >> 5;
    const int mt = bid & 31, n0 = (bid >> 5) * 32;
    const int rowA = d_srt[bid], rowB = d_srt[NBLK-1-bid];
    const int hA = d_half[rowA];
    const int hB = d_half[rowB], LB = lens[rowB];

    {
        const float4* src = (const float4*)(d_W1t + (size_t)mt*512*64);
        float4* dst = (float4*)sm->Ws;
        for (int i = tid; i < 512*64/4; i += 1024) dst[i] = src[i];
    }
    __syncthreads();

    for (int step = 0; step < ML; step++) {
        const int p = step & 1;

        // ===== LSTM1: k-split 8, 64 k per group =====
        {
            const float* h1in = d_h1[p];
            {
                int an = tid & 31, kb = tid >> 5;
                const float* src = h1in + (size_t)(n0 + an)*HH + kb*16;
                #pragma unroll
                for (int q = 0; q < 4; q++) {
                    float4 v = __ldcg((const float4*)(src + q*4));
                    int kk = kb*16 + q*4;
                    sm->u.As1[kk][an] = v.x; sm->u.As1[kk+1][an] = v.y;
                    sm->u.As1[kk+2][an] = v.z; sm->u.As1[kk+3][an] = v.w;
                }
            }
            __syncthreads();
            const int g = tid >> 7, t = tid & 127;
            const int np = t & 7, c4 = t >> 3;
            ull acc[8] = {0,0,0,0,0,0,0,0};
            #pragma unroll 4
            for (int k = 0; k < 64; k++) {
                const float* ar = &sm->u.As1[g*64 + k][np*4];
                ull a0 = *(const ull*)ar, a1 = *(const ull*)(ar + 2);
                float4 w = *(const float4*)&sm->Ws[g*64 + k][c4*4];
                ull b0 = pack2(w.x), b1 = pack2(w.y), b2 = pack2(w.z), b3 = pack2(w.w);
                ffma2(acc[0],a0,b0); ffma2(acc[1],a1,b0);
                ffma2(acc[2],a0,b1); ffma2(acc[3],a1,b1);
                ffma2(acc[4],a0,b2); ffma2(acc[5],a1,b2);
                ffma2(acc[6],a0,b3); ffma2(acc[7],a1,b3);
            }
            __syncthreads();
            #pragma unroll
            for (int j = 0; j < 4; j++) {
                float2 v0 = unpack2(acc[2*j]), v1 = unpack2(acc[2*j+1]);
                float* gr = sm->u.gt1[g][c4*4 + j];
                gr[np*4] = v0.x; gr[np*4+1] = v0.y; gr[np*4+2] = v1.x; gr[np*4+3] = v1.y;
            }
            __syncthreads();
            if (tid < 512) {
                int nl = tid >> 4, mi = tid & 15;
                int gn = n0 + nl, gm = mt*16 + mi;
                int tk = __ldcg(&d_tok[gn]);
                const float* tt = d_toktab + (size_t)tk*G1;
                const float* ic = d_inpc + (size_t)gn*G1;
                float g4[4];
                #pragma unroll
                for (int gg = 0; gg < 4; gg++) {
                    int col = gg*16 + mi;
                    float s = 0.f;
                    #pragma unroll
                    for (int w = 0; w < 8; w++) s += sm->u.gt1[w][col][nl];
                    g4[gg] = s + tt[gg*HH + gm] + ic[gg*HH + gm];
                }
                float cp = d_c1[gn*HH + gm];
                float cn = sigf(g4[1])*cp + sigf(g4[0])*tanhf(g4[2]);
                d_c1[gn*HH + gm] = cn;
                d_h1[p^1][gn*HH + gm] = sigf(g4[3])*tanhf(cn);
            }
        }
        grid_bar();

        // ===== LSTM2: k-split 16, 40 k per group =====
        {
            const float* h1n = d_h1[p^1];
            const float* h2p = d_h2[p];
            {
                int an = tid & 31, kb = tid >> 5;
                #pragma unroll
                for (int q = 0; q < 5; q++) {
                    int kk = kb*20 + q*4;
                    float4 v = (kk < 512)
                        ? __ldcg((const float4*)(h1n + (size_t)(n0 + an)*HH  + kk))
                        : __ldcg((const float4*)(h2p + (size_t)(n0 + an)*KSZ + kk - 512));
                    sm->u.As2[kk][an] = v.x; sm->u.As2[kk+1][an] = v.y;
                    sm->u.As2[kk+2][an] = v.z; sm->u.As2[kk+3][an] = v.w;
                }
            }
            __syncthreads();
            const int g2 = tid >> 6, t2 = tid & 63;
            const int np = t2 & 7, c2 = t2 >> 3;
            const int kb2 = g2 * 40;
            const ulonglong2* bp = (const ulonglong2*)d_W2d + ((size_t)mt*640 + kb2)*8 + c2;
            ull A00=0, A01=0, A10=0, A11=0;
            #pragma unroll 8
            for (int k = 0; k < 40; k++) {
                const float* ar = &sm->u.As2[kb2 + k][np*4];
                ull a0 = *(const ull*)ar, a1 = *(const ull*)(ar + 2);
                ulonglong2 b = bp[(size_t)k*8];
                ffma2(A00, a0, b.x); ffma2(A10, a1, b.x);
                ffma2(A01, a0, b.y); ffma2(A11, a1, b.y);
            }
            __syncthreads();
            { float2 v;
              v = unpack2(A00); sm->u.l2b.gt[g2][2*c2  ][np*4  ] = v.x; sm->u.l2b.gt[g2][2*c2  ][np*4+1] = v.y;
              v = unpack2(A10); sm->u.l2b.gt[g2][2*c2  ][np*4+2] = v.x; sm->u.l2b.gt[g2][2*c2  ][np*4+3] = v.y;
              v = unpack2(A01); sm->u.l2b.gt[g2][2*c2+1][np*4  ] = v.x; sm->u.l2b.gt[g2][2*c2+1][np*4+1] = v.y;
              v = unpack2(A11); sm->u.l2b.gt[g2][2*c2+1][np*4+2] = v.x; sm->u.l2b.gt[g2][2*c2+1][np*4+3] = v.y; }
            __syncthreads();
            if (tid < 512) {
                int cc = tid & 15, nl = tid >> 4;
                float s = 0.f;
                #pragma unroll
                for (int w = 0; w < 16; w++) s += sm->u.l2b.gt[w][cc][nl];
                sm->u.l2b.rs[cc][nl] = s;
            }
            __syncthreads();
            if (tid < 128) {
                int nl = tid >> 2, ci = tid & 3;
                int gn = n0 + nl, gm = mt*4 + ci;
                float g4[4];
                #pragma unroll
                for (int gg = 0; gg < 4; gg++) {
                    int r = gg*KSZ + gm;
                    g4[gg] = sm->u.l2b.rs[gg*4 + ci][nl] + bih2[r] + bhh2[r];
                }
                float cp = d_c2[gn*KSZ + gm];
                float cn = sigf(g4[1])*cp + sigf(g4[0])*tanhf(g4[2]);
                d_c2[gn*KSZ + gm] = cn;
                d_h2[p^1][gn*KSZ + gm] = sigf(g4[3])*tanhf(cn);
            }
        }
        grid_bar();

        // ===== attention partials: 2 balanced units =====
        attn_part(sm, key, val, d_h2[p^1] + (size_t)rowA*KSZ, rowA, 0, 0, hA);
        attn_part(sm, key, val, d_h2[p^1] + (size_t)rowB*KSZ, rowB, 1, hB, LB - hB);
        grid_bar();

        // ===== combine + output proj + argmax =====
        {
            const int n = bid;
            if (tid < KSZ) sm->u.at.h2s[tid] = __ldcg(&d_h2[p^1][(size_t)n*KSZ + tid]);
            if (tid == 0) {
                float m0 = __ldcg(&d_pm[2*n]),   m1 = __ldcg(&d_pm[2*n+1]);
                float s0 = __ldcg(&d_ps[2*n]),   s1 = __ldcg(&d_ps[2*n+1]);
                float M = fmaxf(m0, m1);
                float f0 = expf(m0 - M), f1 = expf(m1 - M);
                float S = f0*s0 + f1*s1;
                sm->u.at.cmb[0] = f0; sm->u.at.cmb[1] = f1; sm->u.at.cmb[2] = 1.0f / S;
            }
            __syncthreads();
            if (tid < VS) {
                float c0 = __ldcg(&d_pctx[(size_t)(2*n)*VS + tid]);
                float c1 = __ldcg(&d_pctx[(size_t)(2*n+1)*VS + tid]);
                sm->u.at.ctxs[tid] = (sm->u.at.cmb[0]*c0 + sm->u.at.cmb[1]*c1) * sm->u.at.cmb[2];
            }
            __syncthreads();
            for (int v = wid; v < VV; v += 32) {
                const float* wr = Wout + (size_t)v*(KSZ+VS);
                float s = 0.f;
                #pragma unroll
                for (int kk = 0; kk < 8; kk++) {
                    int k = lane + kk*32;
                    float x = (k < KSZ) ? sm->u.at.h2s[k] : sm->u.at.ctxs[k-KSZ];
                    s += x * wr[k];
                }
                #pragma unroll
                for (int sh = 16; sh; sh >>= 1) s += __shfl_xor_sync(~0u, s, sh);
                if (lane == 0) sm->u.at.preds[v] = s + bout[v];
            }
            __syncthreads();
            if (tid < VV) out[(size_t)n*ML*VV + (size_t)step*VV + tid] = sm->u.at.preds[tid];
            if (tid == 0) {
                float best = sm->u.at.preds[0]; int bi = 0;
                #pragma unroll
                for (int v = 1; v < VV; v++)
                    if (sm->u.at.preds[v] > best) { best = sm->u.at.preds[v]; bi = v; }
                d_tok[n] = bi;
            }
        }
        grid_bar();
    }
}

extern "C" void kernel_launch(void* const* d_in, const int* in_sizes, int n_in,
                              void* d_out, int out_size) {
    const float* key  = (const float*)d_in[0];
    const float* val  = (const float*)d_in[1];
    const int*   lens = (const int*)  d_in[2];
    const float* emb  = (const float*)d_in[3];
    const float* Wih1 = (const float*)d_in[4];
    const float* Whh1 = (const float*)d_in[5];
    const float* bih1 = (const float*)d_in[6];
    const float* bhh1 = (const float*)d_in[7];
    const float* Wih2 = (const float*)d_in[8];
    const float* Whh2 = (const float*)d_in[9];
    const float* bih2 = (const float*)d_in[10];
    const float* bhh2 = (const float*)d_in[11];
    const float* Wout = (const float*)d_in[12];
    const float* bout = (const float*)d_in[13];
    float* out = (float*)d_out;

    cudaFuncSetAttribute(k_decode, cudaFuncAttributeMaxDynamicSharedMemorySize,
                         (int)sizeof(SMem));
    k_pre<<<NB, 256>>>(val, emb, Wih1, bih1, bhh1, Whh1, Wih2, Whh2, lens);
    k_decode<<<NBLK, 1024, sizeof(SMem)>>>(key, val, lens, bih2, bhh2, Wout, bout, out);
}

// round 15
// speedup vs baseline: 1.5613x; 1.5613x over previous
#include <cuda_runtime.h>

#define TT  1024
#define NB  128
#define VV  35
#define HH  512
#define VS  128
#define KSZ 128
#define G1  2048
#define ML  250
#define NBLK 128

typedef unsigned long long ull;

__device__ float d_inpc[NB*G1];
__device__ float d_toktab[VV*G1];
__device__ float d_h1[2][NB*HH];
__device__ float d_c1[NB*HH];
__device__ float d_h2[2][NB*KSZ];
__device__ float d_c2[NB*KSZ];
__device__ int   d_tok[NB];
__device__ unsigned d_barcnt, d_bargen, d_tokcnt;
__device__ float  d_W1t[32*512*64];
__device__ float4 d_W2d[32*640*8];
__device__ int    d_srt[NB];
__device__ int    d_half[NB];
__device__ float  d_pm[NB*2], d_ps[NB*2];
__device__ float  d_pctx[NB*2*VS];

__device__ __forceinline__ ull pack2(float x) {
    unsigned r = __float_as_uint(x); ull d;
    asm("mov.b64 %0, {%1, %2};" : "=l"(d) : "r"(r), "r"(r));
    return d;
}
__device__ __forceinline__ void ffma2(ull& c, ull a, ull b) {
    asm("fma.rn.f32x2 %0, %1, %2, %0;" : "+l"(c) : "l"(a), "l"(b));
}
__device__ __forceinline__ float2 unpack2(ull v) {
    unsigned lo, hi;
    asm("mov.b64 {%0, %1}, %2;" : "=r"(lo), "=r"(hi) : "l"(v));
    return make_float2(__uint_as_float(lo), __uint_as_float(hi));
}
__device__ __forceinline__ float sigf(float x) { return 1.0f / (1.0f + expf(-x)); }

// full barrier: entry fence kept (write->flag order); exit fence removed
// (all cross-block reads after barriers use __ldcg / are same-thread)
__device__ __forceinline__ void grid_bar() {
    __threadfence();
    __syncthreads();
    if (threadIdx.x == 0) {
        volatile unsigned* genp = &d_bargen;
        unsigned gen = *genp;
        if (atomicAdd(&d_barcnt, 1u) == NBLK - 1) {
            d_barcnt = 0; __threadfence(); *genp = gen + 1;
        } else { while (*genp == gen) { } }
    }
    __syncthreads();
}

__global__ void __launch_bounds__(256) k_pre(const float* __restrict__ val,
        const float* __restrict__ emb, const float* __restrict__ Wih1,
        const float* __restrict__ bih1, const float* __restrict__ bhh1,
        const float* __restrict__ Whh1, const float* __restrict__ Wih2,
        const float* __restrict__ Whh2, const int* __restrict__ lens) {
    __shared__ float vp[2][VS];
    __shared__ float vm[VS];
    __shared__ float e[HH];
    int n = blockIdx.x, tid = threadIdx.x;
    {
        int ch = tid & 127, hp = tid >> 7;
        const float* p = val + (size_t)hp*NB*VS + n*VS + ch;
        float s = 0.f;
        #pragma unroll 8
        for (int t = 0; t < TT/2; t++) s += p[(size_t)t*2*NB*VS];
        vp[hp][ch] = s;
    }
    __syncthreads();
    if (tid < VS) vm[tid] = (vp[0][tid] + vp[1][tid]) * (1.0f/TT);
    __syncthreads();
    for (int j = tid; j < G1; j += 256) {
        const float4* w4 = (const float4*)(Wih1 + (size_t)j*(HH+VS) + HH);
        float s = 0.f;
        #pragma unroll 8
        for (int v = 0; v < VS/4; v++) {
            float4 w = w4[v];
            s += w.x*vm[4*v] + w.y*vm[4*v+1] + w.z*vm[4*v+2] + w.w*vm[4*v+3];
        }
        d_inpc[n*G1 + j] = s + bih1[j] + bhh1[j];
    }
    if (n < VV) {
        for (int k = tid; k < HH; k += 256) e[k] = emb[n*HH + k];
        __syncthreads();
        for (int j = tid; j < G1; j += 256) {
            const float4* w4 = (const float4*)(Wih1 + (size_t)j*(HH+VS));
            float s = 0.f;
            #pragma unroll 8
            for (int k = 0; k < HH/4; k++) {
                float4 w = w4[k];
                s += w.x*e[4*k] + w.y*e[4*k+1] + w.z*e[4*k+2] + w.w*e[4*k+3];
            }
            d_toktab[n*G1 + j] = s;
        }
    }
    int mt = n & 31, kq = n >> 5;
    for (int idx = tid; idx < 128*64; idx += 256) {
        int kk = kq*128 + (idx >> 6), c = idx & 63;
        int r = (c >> 4)*HH + mt*16 + (c & 15);
        d_W1t[((size_t)mt*512 + kk)*64 + c] = Whh1[(size_t)r*HH + kk];
    }
    for (int idx = tid; idx < 160*8; idx += 256) {
        int kk = kq*160 + (idx >> 3), c2 = idx & 7;
        int j0 = 2*c2, j1 = j0 + 1;
        int r0 = (j0 >> 2)*KSZ + mt*4 + (j0 & 3);
        int r1 = (j1 >> 2)*KSZ + mt*4 + (j1 & 3);
        float w0 = (kk < 512) ? Wih2[(size_t)r0*HH + kk] : Whh2[(size_t)r0*KSZ + kk - 512];
        float w1 = (kk < 512) ? Wih2[(size_t)r1*HH + kk] : Whh2[(size_t)r1*KSZ + kk - 512];
        d_W2d[((size_t)mt*640 + kk)*8 + c2] = make_float4(w0, w0, w1, w1);
    }
    for (int i = tid; i < HH; i += 256) { d_h1[0][n*HH+i] = 0.f; d_c1[n*HH+i] = 0.f; }
    if (tid < KSZ) { d_h2[0][n*KSZ+tid] = 0.f; d_c2[n*KSZ+tid] = 0.f; }
    if (tid == 0) {
        d_tok[n] = 0;
        int L = lens[n];
        int h = (((L + 1) >> 1) + 15) & ~15;
        d_half[n] = (h > L) ? L : h;
    }
    if (n == 0 && tid == 0) {
        d_tokcnt = 0;
        int ord[NB];
        for (int i = 0; i < NB; i++) ord[i] = i;
        for (int i = 0; i < NB-1; i++) {
            int bi = i;
            for (int j = i+1; j < NB; j++)
                if (lens[ord[j]] > lens[ord[bi]]) bi = j;
            int tmp = ord[i]; ord[i] = ord[bi]; ord[bi] = tmp;
        }
        for (int i = 0; i < NB; i++) d_srt[i] = ord[i];
    }
}

struct SMem {
    float Ws[512][64];
    union {
        float As1[512][34];
        float gt1[4][64][33];
        float As2[640][34];
        struct { float gt[8][16][33]; float rs[16][33]; } l2b;
        struct { float h2s[KSZ]; float ev[528]; float cpart[16][VS]; float ctxs[VS];
                 float preds[VV]; float red[16], red2[16]; float cmb[4]; } at;
    } u;
};

__device__ void attn_part(SMem* sm, const float* __restrict__ key,
        const float* __restrict__ val, const float* __restrict__ h2row,
        int n, int ci, int t0, int tl) {
    const int tid = threadIdx.x, lane = tid & 31, wid = tid >> 5;
    float* ev = sm->u.at.ev;
    __syncthreads();
    if (tid < KSZ) sm->u.at.h2s[tid] = __ldcg(&h2row[tid]);
    __syncthreads();
    const float* krow = key + (size_t)t0*(NB*KSZ) + (size_t)n*KSZ + lane*4;
    const float* vrow = val + (size_t)t0*(NB*VS)  + (size_t)n*VS  + lane*4;
    float4 hv = *(const float4*)&sm->u.at.h2s[lane*4];
    float wmax = -3.0e38f;
    int t = wid;
    for (; t + 48 < tl; t += 64) {
        float4 k0 = *(const float4*)(krow + (size_t)(t     )*(NB*KSZ));
        float4 k1 = *(const float4*)(krow + (size_t)(t + 16)*(NB*KSZ));
        float4 k2 = *(const float4*)(krow + (size_t)(t + 32)*(NB*KSZ));
        float4 k3 = *(const float4*)(krow + (size_t)(t + 48)*(NB*KSZ));
        float s0 = k0.x*hv.x + k0.y*hv.y + k0.z*hv.z + k0.w*hv.w;
        float s1 = k1.x*hv.x + k1.y*hv.y + k1.z*hv.z + k1.w*hv.w;
        float s2 = k2.x*hv.x + k2.y*hv.y + k2.z*hv.z + k2.w*hv.w;
        float s3 = k3.x*hv.x + k3.y*hv.y + k3.z*hv.z + k3.w*hv.w;
        #pragma unroll
        for (int sh = 16; sh; sh >>= 1) {
            s0 += __shfl_xor_sync(~0u, s0, sh); s1 += __shfl_xor_sync(~0u, s1, sh);
            s2 += __shfl_xor_sync(~0u, s2, sh); s3 += __shfl_xor_sync(~0u, s3, sh);
        }
        if (lane == 0) { ev[t]=s0; ev[t+16]=s1; ev[t+32]=s2; ev[t+48]=s3; }
        wmax = fmaxf(wmax, fmaxf(fmaxf(s0,s1), fmaxf(s2,s3)));
    }
    for (; t < tl; t += 16) {
        float4 k0 = *(const float4*)(krow + (size_t)t*(NB*KSZ));
        float s0 = k0.x*hv.x + k0.y*hv.y + k0.z*hv.z + k0.w*hv.w;
        #pragma unroll
        for (int sh = 16; sh; sh >>= 1) s0 += __shfl_xor_sync(~0u, s0, sh);
        if (lane == 0) ev[t] = s0;
        wmax = fmaxf(wmax, s0);
    }
    if (lane == 0) sm->u.at.red[wid] = wmax;
    __syncthreads();
    float m = sm->u.at.red[0];
    #pragma unroll
    for (int w = 1; w < 16; w++) m = fmaxf(m, sm->u.at.red[w]);
    float psum = 0.f;
    if (tid < tl) { float w = expf(ev[tid] - m); ev[tid] = w; psum += w; }
    #pragma unroll
    for (int sh = 16; sh; sh >>= 1) psum += __shfl_xor_sync(~0u, psum, sh);
    if (lane == 0) sm->u.at.red2[wid] = psum;
    __syncthreads();
    float4 a0 = {0,0,0,0}, a1 = {0,0,0,0};
    t = wid;
    for (; t + 16 < tl; t += 32) {
        float e0 = ev[t], e1 = ev[t+16];
        float4 v0 = *(const float4*)(vrow + (size_t)(t     )*(NB*VS));
        float4 v1 = *(const float4*)(vrow + (size_t)(t + 16)*(NB*VS));
        a0.x += e0*v0.x; a0.y += e0*v0.y; a0.z += e0*v0.z; a0.w += e0*v0.w;
        a1.x += e1*v1.x; a1.y += e1*v1.y; a1.z += e1*v1.z; a1.w += e1*v1.w;
    }
    for (; t < tl; t += 16) {
        float e0 = ev[t];
        float4 v0 = *(const float4*)(vrow + (size_t)t*(NB*VS));
        a0.x += e0*v0.x; a0.y += e0*v0.y; a0.z += e0*v0.z; a0.w += e0*v0.w;
    }
    a0.x += a1.x; a0.y += a1.y; a0.z += a1.z; a0.w += a1.w;
    *(float4*)&sm->u.at.cpart[wid][lane*4] = a0;
    __syncthreads();
    if (tid < VS) {
        float s = 0.f;
        #pragma unroll
        for (int w = 0; w < 16; w++) s += sm->u.at.cpart[w][tid];
        d_pctx[((size_t)n*2 + ci)*VS + tid] = s;
    }
    if (tid == 0) {
        float st = 0.f;
        #pragma unroll
        for (int w = 0; w < 16; w++) st += sm->u.at.red2[w];
        d_pm[n*2 + ci] = m;
        d_ps[n*2 + ci] = st;
    }
}

// combine + output projection + argmax for decode-step `outstep`, row n
__device__ void combine_proj(SMem* sm, const float* __restrict__ Wout,
        const float* __restrict__ bout, float* __restrict__ out,
        const float* __restrict__ h2base, int n, int outstep) {
    const int tid = threadIdx.x, lane = tid & 31, wid = tid >> 5;
    if (tid < KSZ) sm->u.at.h2s[tid] = __ldcg(&h2base[(size_t)n*KSZ + tid]);
    if (tid == 0) {
        float m0 = __ldcg(&d_pm[2*n]),   m1 = __ldcg(&d_pm[2*n+1]);
        float s0 = __ldcg(&d_ps[2*n]),   s1 = __ldcg(&d_ps[2*n+1]);
        float M = fmaxf(m0, m1);
        float f0 = expf(m0 - M), f1 = expf(m1 - M);
        float S = f0*s0 + f1*s1;
        sm->u.at.cmb[0] = f0; sm->u.at.cmb[1] = f1; sm->u.at.cmb[2] = 1.0f / S;
    }
    __syncthreads();
    if (tid < VS) {
        float c0 = __ldcg(&d_pctx[(size_t)(2*n)*VS + tid]);
        float c1 = __ldcg(&d_pctx[(size_t)(2*n+1)*VS + tid]);
        sm->u.at.ctxs[tid] = (sm->u.at.cmb[0]*c0 + sm->u.at.cmb[1]*c1) * sm->u.at.cmb[2];
    }
    __syncthreads();
    for (int v = wid; v < VV; v += 16) {
        const float* wr = Wout + (size_t)v*(KSZ+VS);
        float s = 0.f;
        #pragma unroll
        for (int kk = 0; kk < 8; kk++) {
            int k = lane + kk*32;
            float x = (k < KSZ) ? sm->u.at.h2s[k] : sm->u.at.ctxs[k-KSZ];
            s += x * wr[k];
        }
        #pragma unroll
        for (int sh = 16; sh; sh >>= 1) s += __shfl_xor_sync(~0u, s, sh);
        if (lane == 0) sm->u.at.preds[v] = s + bout[v];
    }
    __syncthreads();
    if (tid < VV) out[(size_t)n*ML*VV + (size_t)outstep*VV + tid] = sm->u.at.preds[tid];
    if (tid == 0) {
        float best = sm->u.at.preds[0]; int bi = 0;
        #pragma unroll
        for (int v = 1; v < VV; v++)
            if (sm->u.at.preds[v] > best) { best = sm->u.at.preds[v]; bi = v; }
        d_tok[n] = bi;
    }
}

__global__ void __launch_bounds__(512, 1) k_decode(
    const float* __restrict__ key, const float* __restrict__ val,
    const int* __restrict__ lens,
    const float* __restrict__ bih2, const float* __restrict__ bhh2,
    const float* __restrict__ Wout, const float* __restrict__ bout,
    float* __restrict__ out)
{
    extern __shared__ __align__(16) char smraw[];
    SMem* sm = (SMem*)smraw;
    const int bid = blockIdx.x, tid = threadIdx.x;
    const int mt = bid & 31, n0 = (bid >> 5) * 32;
    const int rowA = d_srt[bid], rowB = d_srt[NBLK-1-bid];
    const int hA = d_half[rowA];
    const int hB = d_half[rowB], LB = lens[rowB];

    {
        const float4* src = (const float4*)(d_W1t + (size_t)mt*512*64);
        float4* dst = (float4*)sm->Ws;
        for (int i = tid; i < 512*64/4; i += 512) dst[i] = src[i];
    }
    __syncthreads();

    for (int step = 0; step < ML; step++) {
        const int p = step & 1;

        // ===== phase 1: combine(prev) -> arrive tok-bar -> LSTM1 MMA -> wait -> epilogue =====
        {
            if (step > 0)
                combine_proj(sm, Wout, bout, out, d_h2[p], bid, step - 1);
            __threadfence();                 // tok store -> L2 before arrive
            if (tid == 0) atomicAdd(&d_tokcnt, 1u);
            __syncthreads();                 // smem at.* free before As1 staging

            const float* h1in = d_h1[p];
            {
                int an = tid & 31, kb = tid >> 5;
                const float* src = h1in + (size_t)(n0 + an)*HH + kb*32;
                #pragma unroll
                for (int q = 0; q < 8; q++) {
                    float4 v = __ldcg((const float4*)(src + q*4));
                    int kk = kb*32 + q*4;
                    sm->u.As1[kk][an] = v.x; sm->u.As1[kk+1][an] = v.y;
                    sm->u.As1[kk+2][an] = v.z; sm->u.As1[kk+3][an] = v.w;
                }
            }
            __syncthreads();
            const int g = tid >> 7, t = tid & 127;
            const int np = t & 7, c4 = t >> 3;
            ull acc[8] = {0,0,0,0,0,0,0,0};
            #pragma unroll 4
            for (int k = 0; k < 128; k++) {
                const float* ar = &sm->u.As1[g*128 + k][np*4];
                ull a0 = *(const ull*)ar, a1 = *(const ull*)(ar + 2);
                float4 w = *(const float4*)&sm->Ws[g*128 + k][c4*4];
                ull b0 = pack2(w.x), b1 = pack2(w.y), b2 = pack2(w.z), b3 = pack2(w.w);
                ffma2(acc[0],a0,b0); ffma2(acc[1],a1,b0);
                ffma2(acc[2],a0,b1); ffma2(acc[3],a1,b1);
                ffma2(acc[4],a0,b2); ffma2(acc[5],a1,b2);
                ffma2(acc[6],a0,b3); ffma2(acc[7],a1,b3);
            }
            __syncthreads();
            #pragma unroll
            for (int j = 0; j < 4; j++) {
                float2 v0 = unpack2(acc[2*j]), v1 = unpack2(acc[2*j+1]);
                float* gr = sm->u.gt1[g][c4*4 + j];
                gr[np*4] = v0.x; gr[np*4+1] = v0.y; gr[np*4+2] = v1.x; gr[np*4+3] = v1.y;
            }
            // hidden wait: all blocks' tok for this step must be written
            if (tid == 0) {
                unsigned tgt = (unsigned)(NBLK * (step + 1));
                while (*(volatile unsigned*)&d_tokcnt < tgt) { }
            }
            __syncthreads();
            int nl = tid >> 4, mi = tid & 15;
            int gn = n0 + nl, gm = mt*16 + mi;
            int tk = __ldcg(&d_tok[gn]);
            const float* tt = d_toktab + (size_t)tk*G1;
            const float* ic = d_inpc + (size_t)gn*G1;
            float g4[4];
            #pragma unroll
            for (int gg = 0; gg < 4; gg++) {
                int col = gg*16 + mi;
                g4[gg] = sm->u.gt1[0][col][nl] + sm->u.gt1[1][col][nl]
                       + sm->u.gt1[2][col][nl] + sm->u.gt1[3][col][nl]
                       + tt[gg*HH + gm] + ic[gg*HH + gm];
            }
            float cp = d_c1[gn*HH + gm];
            float cn = sigf(g4[1])*cp + sigf(g4[0])*tanhf(g4[2]);
            d_c1[gn*HH + gm] = cn;
            d_h1[p^1][gn*HH + gm] = sigf(g4[3])*tanhf(cn);
        }
        grid_bar();

        // ===== LSTM2 =====
        {
            const float* h1n = d_h1[p^1];
            const float* h2p = d_h2[p];
            {
                int an = tid & 31, kb = tid >> 5;
                #pragma unroll
                for (int q = 0; q < 10; q++) {
                    int kk = kb*40 + q*4;
                    float4 v = (kk < 512)
                        ? __ldcg((const float4*)(h1n + (size_t)(n0 + an)*HH  + kk))
                        : __ldcg((const float4*)(h2p + (size_t)(n0 + an)*KSZ + kk - 512));
                    sm->u.As2[kk][an] = v.x; sm->u.As2[kk+1][an] = v.y;
                    sm->u.As2[kk+2][an] = v.z; sm->u.As2[kk+3][an] = v.w;
                }
            }
            __syncthreads();
            const int g2 = tid >> 6, t2 = tid & 63;
            const int np = t2 & 7, c2 = t2 >> 3;
            const int kb2 = g2 * 80;
            const ulonglong2* bp = (const ulonglong2*)d_W2d + ((size_t)mt*640 + kb2)*8 + c2;
            ull A00=0, A01=0, A10=0, A11=0;
            #pragma unroll 8
            for (int k = 0; k < 80; k++) {
                const float* ar = &sm->u.As2[kb2 + k][np*4];
                ull a0 = *(const ull*)ar, a1 = *(const ull*)(ar + 2);
                ulonglong2 b = bp[(size_t)k*8];
                ffma2(A00, a0, b.x); ffma2(A10, a1, b.x);
                ffma2(A01, a0, b.y); ffma2(A11, a1, b.y);
            }
            __syncthreads();
            { float2 v;
              v = unpack2(A00); sm->u.l2b.gt[g2][2*c2  ][np*4  ] = v.x; sm->u.l2b.gt[g2][2*c2  ][np*4+1] = v.y;
              v = unpack2(A10); sm->u.l2b.gt[g2][2*c2  ][np*4+2] = v.x; sm->u.l2b.gt[g2][2*c2  ][np*4+3] = v.y;
              v = unpack2(A01); sm->u.l2b.gt[g2][2*c2+1][np*4  ] = v.x; sm->u.l2b.gt[g2][2*c2+1][np*4+1] = v.y;
              v = unpack2(A11); sm->u.l2b.gt[g2][2*c2+1][np*4+2] = v.x; sm->u.l2b.gt[g2][2*c2+1][np*4+3] = v.y; }
            __syncthreads();
            {
                int cc = tid & 15, nl = tid >> 4;
                float s = 0.f;
                #pragma unroll
                for (int w = 0; w < 8; w++) s += sm->u.l2b.gt[w][cc][nl];
                sm->u.l2b.rs[cc][nl] = s;
            }
            __syncthreads();
            if (tid < 128) {
                int nl = tid >> 2, ci = tid & 3;
                int gn = n0 + nl, gm = mt*4 + ci;
                float g4[4];
                #pragma unroll
                for (int gg = 0; gg < 4; gg++) {
                    int r = gg*KSZ + gm;
                    g4[gg] = sm->u.l2b.rs[gg*4 + ci][nl] + bih2[r] + bhh2[r];
                }
                float cp = d_c2[gn*KSZ + gm];
                float cn = sigf(g4[1])*cp + sigf(g4[0])*tanhf(g4[2]);
                d_c2[gn*KSZ + gm] = cn;
                d_h2[p^1][gn*KSZ + gm] = sigf(g4[3])*tanhf(cn);
            }
        }
        grid_bar();

        // ===== attention partials: 2 balanced units =====
        attn_part(sm, key, val, d_h2[p^1] + (size_t)rowA*KSZ, rowA, 0, 0, hA);
        attn_part(sm, key, val, d_h2[p^1] + (size_t)rowB*KSZ, rowB, 1, hB, LB - hB);
        grid_bar();
    }

    // final decode step's combine + output
    combine_proj(sm, Wout, bout, out, d_h2[ML & 1], bid, ML - 1);
}

extern "C" void kernel_launch(void* const* d_in, const int* in_sizes, int n_in,
                              void* d_out, int out_size) {
    const float* key  = (const float*)d_in[0];
    const float* val  = (const float*)d_in[1];
    const int*   lens = (const int*)  d_in[2];
    const float* emb  = (const float*)d_in[3];
    const float* Wih1 = (const float*)d_in[4];
    const float* Whh1 = (const float*)d_in[5];
    const float* bih1 = (const float*)d_in[6];
    const float* bhh1 = (const float*)d_in[7];
    const float* Wih2 = (const float*)d_in[8];
    const float* Whh2 = (const float*)d_in[9];
    const float* bih2 = (const float*)d_in[10];
    const float* bhh2 = (const float*)d_in[11];
    const float* Wout = (const float*)d_in[12];
    const float* bout = (const float*)d_in[13];
    float* out = (float*)d_out;

    cudaFuncSetAttribute(k_decode, cudaFuncAttributeMaxDynamicSharedMemorySize,
                         (int)sizeof(SMem));
    k_pre<<<NB, 256>>>(val, emb, Wih1, bih1, bhh1, Whh1, Wih2, Whh2, lens);
    k_decode<<<NBLK, 512, sizeof(SMem)>>>(key, val, lens, bih2, bhh2, Wout, bout, out);
}

// round 16
// speedup vs baseline: 1.6360x; 1.0479x over previous
#include <cuda_runtime.h>

#define TT  1024
#define NB  128
#define VV  35
#define HH  512
#define VS  128
#define KSZ 128
#define G1  2048
#define ML  250
#define NBLK 128

typedef unsigned long long ull;

__device__ float d_inpc[NB*G1];
__device__ float d_toktab[VV*G1];
__device__ float d_h1[2][NB*HH];
__device__ float d_c1[NB*HH];
__device__ float d_h2[2][NB*KSZ];
__device__ float d_c2[NB*KSZ];
__device__ int   d_tok[NB];
__device__ unsigned d_tokcnt;
__device__ unsigned d_cnt1[4], d_cnt2[4];
__device__ unsigned d_pflag[NB*2];
__device__ float  d_W1t[32*512*64];
__device__ float4 d_W2d[32*640*8];
__device__ int    d_srt[NB];
__device__ int    d_half[NB];
__device__ float  d_pm[NB*2], d_ps[NB*2];
__device__ float  d_pctx[NB*2*VS];

__device__ __forceinline__ ull pack2(float x) {
    unsigned r = __float_as_uint(x); ull d;
    asm("mov.b64 %0, {%1, %2};" : "=l"(d) : "r"(r), "r"(r));
    return d;
}
__device__ __forceinline__ void ffma2(ull& c, ull a, ull b) {
    asm("fma.rn.f32x2 %0, %1, %2, %0;" : "+l"(c) : "l"(a), "l"(b));
}
__device__ __forceinline__ float2 unpack2(ull v) {
    unsigned lo, hi;
    asm("mov.b64 {%0, %1}, %2;" : "=r"(lo), "=r"(hi) : "l"(v));
    return make_float2(__uint_as_float(lo), __uint_as_float(hi));
}
__device__ __forceinline__ float sigf(float x) { return 1.0f / (1.0f + expf(-x)); }
__device__ __forceinline__ void spinge(volatile unsigned* p, unsigned tgt) {
    while (*p < tgt) { }
}

__global__ void __launch_bounds__(256) k_pre(const float* __restrict__ val,
        const float* __restrict__ emb, const float* __restrict__ Wih1,
        const float* __restrict__ bih1, const float* __restrict__ bhh1,
        const float* __restrict__ Whh1, const float* __restrict__ Wih2,
        const float* __restrict__ Whh2, const int* __restrict__ lens) {
    __shared__ float vp[2][VS];
    __shared__ float vm[VS];
    __shared__ float e[HH];
    int n = blockIdx.x, tid = threadIdx.x;
    {
        int ch = tid & 127, hp = tid >> 7;
        const float* p = val + (size_t)hp*NB*VS + n*VS + ch;
        float s = 0.f;
        #pragma unroll 8
        for (int t = 0; t < TT/2; t++) s += p[(size_t)t*2*NB*VS];
        vp[hp][ch] = s;
    }
    __syncthreads();
    if (tid < VS) vm[tid] = (vp[0][tid] + vp[1][tid]) * (1.0f/TT);
    __syncthreads();
    for (int j = tid; j < G1; j += 256) {
        const float4* w4 = (const float4*)(Wih1 + (size_t)j*(HH+VS) + HH);
        float s = 0.f;
        #pragma unroll 8
        for (int v = 0; v < VS/4; v++) {
            float4 w = w4[v];
            s += w.x*vm[4*v] + w.y*vm[4*v+1] + w.z*vm[4*v+2] + w.w*vm[4*v+3];
        }
        d_inpc[n*G1 + j] = s + bih1[j] + bhh1[j];
    }
    if (n < VV) {
        for (int k = tid; k < HH; k += 256) e[k] = emb[n*HH + k];
        __syncthreads();
        for (int j = tid; j < G1; j += 256) {
            const float4* w4 = (const float4*)(Wih1 + (size_t)j*(HH+VS));
            float s = 0.f;
            #pragma unroll 8
            for (int k = 0; k < HH/4; k++) {
                float4 w = w4[k];
                s += w.x*e[4*k] + w.y*e[4*k+1] + w.z*e[4*k+2] + w.w*e[4*k+3];
            }
            d_toktab[n*G1 + j] = s;
        }
    }
    int mt = n & 31, kq = n >> 5;
    for (int idx = tid; idx < 128*64; idx += 256) {
        int kk = kq*128 + (idx >> 6), c = idx & 63;
        int r = (c >> 4)*HH + mt*16 + (c & 15);
        d_W1t[((size_t)mt*512 + kk)*64 + c] = Whh1[(size_t)r*HH + kk];
    }
    for (int idx = tid; idx < 160*8; idx += 256) {
        int kk = kq*160 + (idx >> 3), c2 = idx & 7;
        int j0 = 2*c2, j1 = j0 + 1;
        int r0 = (j0 >> 2)*KSZ + mt*4 + (j0 & 3);
        int r1 = (j1 >> 2)*KSZ + mt*4 + (j1 & 3);
        float w0 = (kk < 512) ? Wih2[(size_t)r0*HH + kk] : Whh2[(size_t)r0*KSZ + kk - 512];
        float w1 = (kk < 512) ? Wih2[(size_t)r1*HH + kk] : Whh2[(size_t)r1*KSZ + kk - 512];
        d_W2d[((size_t)mt*640 + kk)*8 + c2] = make_float4(w0, w0, w1, w1);
    }
    for (int i = tid; i < HH; i += 256) { d_h1[0][n*HH+i] = 0.f; d_c1[n*HH+i] = 0.f; }
    if (tid < KSZ) { d_h2[0][n*KSZ+tid] = 0.f; d_c2[n*KSZ+tid] = 0.f; }
    if (tid < 2) d_pflag[n*2 + tid] = 0;
    if (tid == 0) {
        d_tok[n] = 0;
        int L = lens[n];
        int h = (((L + 1) >> 1) + 15) & ~15;
        d_half[n] = (h > L) ? L : h;
    }
    if (n == 0 && tid == 0) {
        d_tokcnt = 0;
        for (int i = 0; i < 4; i++) { d_cnt1[i] = 0; d_cnt2[i] = 0; }
        int ord[NB];
        for (int i = 0; i < NB; i++) ord[i] = i;
        for (int i = 0; i < NB-1; i++) {
            int bi = i;
            for (int j = i+1; j < NB; j++)
                if (lens[ord[j]] > lens[ord[bi]]) bi = j;
            int tmp = ord[i]; ord[i] = ord[bi]; ord[bi] = tmp;
        }
        for (int i = 0; i < NB; i++) d_srt[i] = ord[i];
    }
}

struct SMem {
    float Ws[512][64];
    union {
        float As1[512][34];
        float gt1[4][64][33];
        float As2[640][34];
        struct { float gt[8][16][33]; float rs[16][33]; } l2b;
        struct { float h2s[KSZ]; float ev[528]; float cpart[16][VS]; float ctxs[VS];
                 float preds[VV]; float red[16], red2[16]; float cmb[4]; } at;
    } u;
};

__device__ void attn_part(SMem* sm, const float* __restrict__ key,
        const float* __restrict__ val, const float* __restrict__ h2row,
        int n, int ci, int t0, int tl, int step) {
    const int tid = threadIdx.x, lane = tid & 31, wid = tid >> 5;
    float* ev = sm->u.at.ev;
    __syncthreads();
    if (tid < KSZ) sm->u.at.h2s[tid] = __ldcg(&h2row[tid]);
    __syncthreads();
    const float* krow = key + (size_t)t0*(NB*KSZ) + (size_t)n*KSZ + lane*4;
    const float* vrow = val + (size_t)t0*(NB*VS)  + (size_t)n*VS  + lane*4;
    float4 hv = *(const float4*)&sm->u.at.h2s[lane*4];
    float wmax = -3.0e38f;
    int t = wid;
    for (; t + 48 < tl; t += 64) {
        float4 k0 = *(const float4*)(krow + (size_t)(t     )*(NB*KSZ));
        float4 k1 = *(const float4*)(krow + (size_t)(t + 16)*(NB*KSZ));
        float4 k2 = *(const float4*)(krow + (size_t)(t + 32)*(NB*KSZ));
        float4 k3 = *(const float4*)(krow + (size_t)(t + 48)*(NB*KSZ));
        float s0 = k0.x*hv.x + k0.y*hv.y + k0.z*hv.z + k0.w*hv.w;
        float s1 = k1.x*hv.x + k1.y*hv.y + k1.z*hv.z + k1.w*hv.w;
        float s2 = k2.x*hv.x + k2.y*hv.y + k2.z*hv.z + k2.w*hv.w;
        float s3 = k3.x*hv.x + k3.y*hv.y + k3.z*hv.z + k3.w*hv.w;
        #pragma unroll
        for (int sh = 16; sh; sh >>= 1) {
            s0 += __shfl_xor_sync(~0u, s0, sh); s1 += __shfl_xor_sync(~0u, s1, sh);
            s2 += __shfl_xor_sync(~0u, s2, sh); s3 += __shfl_xor_sync(~0u, s3, sh);
        }
        if (lane == 0) { ev[t]=s0; ev[t+16]=s1; ev[t+32]=s2; ev[t+48]=s3; }
        wmax = fmaxf(wmax, fmaxf(fmaxf(s0,s1), fmaxf(s2,s3)));
    }
    for (; t < tl; t += 16) {
        float4 k0 = *(const float4*)(krow + (size_t)t*(NB*KSZ));
        float s0 = k0.x*hv.x + k0.y*hv.y + k0.z*hv.z + k0.w*hv.w;
        #pragma unroll
        for (int sh = 16; sh; sh >>= 1) s0 += __shfl_xor_sync(~0u, s0, sh);
        if (lane == 0) ev[t] = s0;
        wmax = fmaxf(wmax, s0);
    }
    if (lane == 0) sm->u.at.red[wid] = wmax;
    __syncthreads();
    float m = sm->u.at.red[0];
    #pragma unroll
    for (int w = 1; w < 16; w++) m = fmaxf(m, sm->u.at.red[w]);
    float psum = 0.f;
    if (tid < tl) { float w = expf(ev[tid] - m); ev[tid] = w; psum += w; }
    #pragma unroll
    for (int sh = 16; sh; sh >>= 1) psum += __shfl_xor_sync(~0u, psum, sh);
    if (lane == 0) sm->u.at.red2[wid] = psum;
    __syncthreads();
    float4 a0 = {0,0,0,0}, a1 = {0,0,0,0};
    t = wid;
    for (; t + 16 < tl; t += 32) {
        float e0 = ev[t], e1 = ev[t+16];
        float4 v0 = *(const float4*)(vrow + (size_t)(t     )*(NB*VS));
        float4 v1 = *(const float4*)(vrow + (size_t)(t + 16)*(NB*VS));
        a0.x += e0*v0.x; a0.y += e0*v0.y; a0.z += e0*v0.z; a0.w += e0*v0.w;
        a1.x += e1*v1.x; a1.y += e1*v1.y; a1.z += e1*v1.z; a1.w += e1*v1.w;
    }
    for (; t < tl; t += 16) {
        float e0 = ev[t];
        float4 v0 = *(const float4*)(vrow + (size_t)t*(NB*VS));
        a0.x += e0*v0.x; a0.y += e0*v0.y; a0.z += e0*v0.z; a0.w += e0*v0.w;
    }
    a0.x += a1.x; a0.y += a1.y; a0.z += a1.z; a0.w += a1.w;
    *(float4*)&sm->u.at.cpart[wid][lane*4] = a0;
    __syncthreads();
    if (tid < VS) {
        float s = 0.f;
        #pragma unroll
        for (int w = 0; w < 16; w++) s += sm->u.at.cpart[w][tid];
        d_pctx[((size_t)n*2 + ci)*VS + tid] = s;
    }
    if (tid == 0) {
        float st = 0.f;
        #pragma unroll
        for (int w = 0; w < 16; w++) st += sm->u.at.red2[w];
        d_pm[n*2 + ci] = m;
        d_ps[n*2 + ci] = st;
    }
    __threadfence();
    __syncthreads();
    if (tid == 0) *(volatile unsigned*)&d_pflag[n*2 + ci] = (unsigned)(step + 1);
}

// combine for decode step `outstep`: spins on its 2 producer flags internally
__device__ void combine_proj(SMem* sm, const float* __restrict__ Wout,
        const float* __restrict__ bout, float* __restrict__ out,
        const float* __restrict__ h2base, int n, int outstep) {
    const int tid = threadIdx.x, lane = tid & 31, wid = tid >> 5;
    if (tid == 0) {
        unsigned tgt = (unsigned)(outstep + 1);
        spinge(&d_pflag[2*n], tgt);
        spinge(&d_pflag[2*n+1], tgt);
    }
    __syncthreads();
    if (tid < KSZ) sm->u.at.h2s[tid] = __ldcg(&h2base[(size_t)n*KSZ + tid]);
    if (tid == 0) {
        float m0 = __ldcg(&d_pm[2*n]),   m1 = __ldcg(&d_pm[2*n+1]);
        float s0 = __ldcg(&d_ps[2*n]),   s1 = __ldcg(&d_ps[2*n+1]);
        float M = fmaxf(m0, m1);
        float f0 = expf(m0 - M), f1 = expf(m1 - M);
        float S = f0*s0 + f1*s1;
        sm->u.at.cmb[0] = f0; sm->u.at.cmb[1] = f1; sm->u.at.cmb[2] = 1.0f / S;
    }
    __syncthreads();
    if (tid < VS) {
        float c0 = __ldcg(&d_pctx[(size_t)(2*n)*VS + tid]);
        float c1 = __ldcg(&d_pctx[(size_t)(2*n+1)*VS + tid]);
        sm->u.at.ctxs[tid] = (sm->u.at.cmb[0]*c0 + sm->u.at.cmb[1]*c1) * sm->u.at.cmb[2];
    }
    __syncthreads();
    for (int v = wid; v < VV; v += 16) {
        const float* wr = Wout + (size_t)v*(KSZ+VS);
        float s = 0.f;
        #pragma unroll
        for (int kk = 0; kk < 8; kk++) {
            int k = lane + kk*32;
            float x = (k < KSZ) ? sm->u.at.h2s[k] : sm->u.at.ctxs[k-KSZ];
            s += x * wr[k];
        }
        #pragma unroll
        for (int sh = 16; sh; sh >>= 1) s += __shfl_xor_sync(~0u, s, sh);
        if (lane == 0) sm->u.at.preds[v] = s + bout[v];
    }
    __syncthreads();
    if (tid < VV) out[(size_t)n*ML*VV + (size_t)outstep*VV + tid] = sm->u.at.preds[tid];
    if (tid == 0) {
        float best = sm->u.at.preds[0]; int bi = 0;
        #pragma unroll
        for (int v = 1; v < VV; v++)
            if (sm->u.at.preds[v] > best) { best = sm->u.at.preds[v]; bi = v; }
        d_tok[n] = bi;
    }
}

__global__ void __launch_bounds__(512, 1) k_decode(
    const float* __restrict__ key, const float* __restrict__ val,
    const int* __restrict__ lens,
    const float* __restrict__ bih2, const float* __restrict__ bhh2,
    const float* __restrict__ Wout, const float* __restrict__ bout,
    float* __restrict__ out)
{
    extern __shared__ __align__(16) char smraw[];
    SMem* sm = (SMem*)smraw;
    const int bid = blockIdx.x, tid = threadIdx.x;
    const int mt = bid & 31, n0 = (bid >> 5) * 32, nt = bid >> 5;
    const int rowA = d_srt[bid], rowB = d_srt[NBLK-1-bid];
    const int hA = d_half[rowA];
    const int hB = d_half[rowB], LB = lens[rowB];
    const int ntA = rowA >> 5, ntB = rowB >> 5;

    {
        const float4* src = (const float4*)(d_W1t + (size_t)mt*512*64);
        float4* dst = (float4*)sm->Ws;
        for (int i = tid; i < 512*64/4; i += 512) dst[i] = src[i];
    }
    __syncthreads();

    for (int step = 0; step < ML; step++) {
        const int p = step & 1;

        // ===== phase 1: combine(prev) -> tok arrive -> LSTM1 MMA -> tok wait -> epilogue =====
        {
            if (step > 0)
                combine_proj(sm, Wout, bout, out, d_h2[p], bid, step - 1);
            __threadfence();
            if (tid == 0) atomicAdd(&d_tokcnt, 1u);
            __syncthreads();

            const float* h1in = d_h1[p];
            {
                int an = tid & 31, kb = tid >> 5;
                const float* src = h1in + (size_t)(n0 + an)*HH + kb*32;
                #pragma unroll
                for (int q = 0; q < 8; q++) {
                    float4 v = __ldcg((const float4*)(src + q*4));
                    int kk = kb*32 + q*4;
                    sm->u.As1[kk][an] = v.x; sm->u.As1[kk+1][an] = v.y;
                    sm->u.As1[kk+2][an] = v.z; sm->u.As1[kk+3][an] = v.w;
                }
            }
            __syncthreads();
            const int g = tid >> 7, t = tid & 127;
            const int np = t & 7, c4 = t >> 3;
            ull acc[8] = {0,0,0,0,0,0,0,0};
            #pragma unroll 4
            for (int k = 0; k < 128; k++) {
                const float* ar = &sm->u.As1[g*128 + k][np*4];
                ull a0 = *(const ull*)ar, a1 = *(const ull*)(ar + 2);
                float4 w = *(const float4*)&sm->Ws[g*128 + k][c4*4];
                ull b0 = pack2(w.x), b1 = pack2(w.y), b2 = pack2(w.z), b3 = pack2(w.w);
                ffma2(acc[0],a0,b0); ffma2(acc[1],a1,b0);
                ffma2(acc[2],a0,b1); ffma2(acc[3],a1,b1);
                ffma2(acc[4],a0,b2); ffma2(acc[5],a1,b2);
                ffma2(acc[6],a0,b3); ffma2(acc[7],a1,b3);
            }
            __syncthreads();
            #pragma unroll
            for (int j = 0; j < 4; j++) {
                float2 v0 = unpack2(acc[2*j]), v1 = unpack2(acc[2*j+1]);
                float* gr = sm->u.gt1[g][c4*4 + j];
                gr[np*4] = v0.x; gr[np*4+1] = v0.y; gr[np*4+2] = v1.x; gr[np*4+3] = v1.y;
            }
            if (tid == 0) spinge(&d_tokcnt, (unsigned)(NBLK * (step + 1)));
            __syncthreads();
            int nl = tid >> 4, mi = tid & 15;
            int gn = n0 + nl, gm = mt*16 + mi;
            int tk = __ldcg(&d_tok[gn]);
            const float* tt = d_toktab + (size_t)tk*G1;
            const float* ic = d_inpc + (size_t)gn*G1;
            float g4[4];
            #pragma unroll
            for (int gg = 0; gg < 4; gg++) {
                int col = gg*16 + mi;
                g4[gg] = sm->u.gt1[0][col][nl] + sm->u.gt1[1][col][nl]
                       + sm->u.gt1[2][col][nl] + sm->u.gt1[3][col][nl]
                       + tt[gg*HH + gm] + ic[gg*HH + gm];
            }
            float cp = d_c1[gn*HH + gm];
            float cn = sigf(g4[1])*cp + sigf(g4[0])*tanhf(g4[2]);
            d_c1[gn*HH + gm] = cn;
            d_h1[p^1][gn*HH + gm] = sigf(g4[3])*tanhf(cn);
            __threadfence();
            __syncthreads();
            if (tid == 0) atomicAdd(&d_cnt1[nt], 1u);
        }

        // ===== LSTM2: wait own n-tile's 32 lstm1 producers (+ own h2 tile) =====
        {
            if (tid == 0) {
                spinge(&d_cnt1[nt], (unsigned)(32 * (step + 1)));
                if (step > 0) spinge(&d_cnt2[nt], (unsigned)(32 * step));
            }
            __syncthreads();
            const float* h1n = d_h1[p^1];
            const float* h2p = d_h2[p];
            {
                int an = tid & 31, kb = tid >> 5;
                #pragma unroll
                for (int q = 0; q < 10; q++) {
                    int kk = kb*40 + q*4;
                    float4 v = (kk < 512)
                        ? __ldcg((const float4*)(h1n + (size_t)(n0 + an)*HH  + kk))
                        : __ldcg((const float4*)(h2p + (size_t)(n0 + an)*KSZ + kk - 512));
                    sm->u.As2[kk][an] = v.x; sm->u.As2[kk+1][an] = v.y;
                    sm->u.As2[kk+2][an] = v.z; sm->u.As2[kk+3][an] = v.w;
                }
            }
            __syncthreads();
            const int g2 = tid >> 6, t2 = tid & 63;
            const int np = t2 & 7, c2 = t2 >> 3;
            const int kb2 = g2 * 80;
            const ulonglong2* bp = (const ulonglong2*)d_W2d + ((size_t)mt*640 + kb2)*8 + c2;
            ull A00=0, A01=0, A10=0, A11=0;
            #pragma unroll 8
            for (int k = 0; k < 80; k++) {
                const float* ar = &sm->u.As2[kb2 + k][np*4];
                ull a0 = *(const ull*)ar, a1 = *(const ull*)(ar + 2);
                ulonglong2 b = bp[(size_t)k*8];
                ffma2(A00, a0, b.x); ffma2(A10, a1, b.x);
                ffma2(A01, a0, b.y); ffma2(A11, a1, b.y);
            }
            __syncthreads();
            { float2 v;
              v = unpack2(A00); sm->u.l2b.gt[g2][2*c2  ][np*4  ] = v.x; sm->u.l2b.gt[g2][2*c2  ][np*4+1] = v.y;
              v = unpack2(A10); sm->u.l2b.gt[g2][2*c2  ][np*4+2] = v.x; sm->u.l2b.gt[g2][2*c2  ][np*4+3] = v.y;
              v = unpack2(A01); sm->u.l2b.gt[g2][2*c2+1][np*4  ] = v.x; sm->u.l2b.gt[g2][2*c2+1][np*4+1] = v.y;
              v = unpack2(A11); sm->u.l2b.gt[g2][2*c2+1][np*4+2] = v.x; sm->u.l2b.gt[g2][2*c2+1][np*4+3] = v.y; }
            __syncthreads();
            {
                int cc = tid & 15, nl = tid >> 4;
                float s = 0.f;
                #pragma unroll
                for (int w = 0; w < 8; w++) s += sm->u.l2b.gt[w][cc][nl];
                sm->u.l2b.rs[cc][nl] = s;
            }
            __syncthreads();
            if (tid < 128) {
                int nl = tid >> 2, ci = tid & 3;
                int gn = n0 + nl, gm = mt*4 + ci;
                float g4[4];
                #pragma unroll
                for (int gg = 0; gg < 4; gg++) {
                    int r = gg*KSZ + gm;
                    g4[gg] = sm->u.l2b.rs[gg*4 + ci][nl] + bih2[r] + bhh2[r];
                }
                float cp = d_c2[gn*KSZ + gm];
                float cn = sigf(g4[1])*cp + sigf(g4[0])*tanhf(g4[2]);
                d_c2[gn*KSZ + gm] = cn;
                d_h2[p^1][gn*KSZ + gm] = sigf(g4[3])*tanhf(cn);
            }
            __threadfence();
            __syncthreads();
            if (tid == 0) atomicAdd(&d_cnt2[nt], 1u);
        }

        // ===== attention partials: wait only rows' h2 tiles =====
        {
            if (tid == 0) {
                unsigned tgt = (unsigned)(32 * (step + 1));
                spinge(&d_cnt2[ntA], tgt);
                spinge(&d_cnt2[ntB], tgt);
            }
            __syncthreads();
            attn_part(sm, key, val, d_h2[p^1] + (size_t)rowA*KSZ, rowA, 0, 0, hA, step);
            attn_part(sm, key, val, d_h2[p^1] + (size_t)rowB*KSZ, rowB, 1, hB, LB - hB, step);
        }
    }

    combine_proj(sm, Wout, bout, out, d_h2[ML & 1], bid, ML - 1);
}

extern "C" void kernel_launch(void* const* d_in, const int* in_sizes, int n_in,
                              void* d_out, int out_size) {
    const float* key  = (const float*)d_in[0];
    const float* val  = (const float*)d_in[1];
    const int*   lens = (const int*)  d_in[2];
    const float* emb  = (const float*)d_in[3];
    const float* Wih1 = (const float*)d_in[4];
    const float* Whh1 = (const float*)d_in[5];
    const float* bih1 = (const float*)d_in[6];
    const float* bhh1 = (const float*)d_in[7];
    const float* Wih2 = (const float*)d_in[8];
    const float* Whh2 = (const float*)d_in[9];
    const float* bih2 = (const float*)d_in[10];
    const float* bhh2 = (const float*)d_in[11];
    const float* Wout = (const float*)d_in[12];
    const float* bout = (const float*)d_in[13];
    float* out = (float*)d_out;

    cudaFuncSetAttribute(k_decode, cudaFuncAttributeMaxDynamicSharedMemorySize,
                         (int)sizeof(SMem));
    k_pre<<<NB, 256>>>(val, emb, Wih1, bih1, bhh1, Whh1, Wih2, Whh2, lens);
    k_decode<<<NBLK, 512, sizeof(SMem)>>>(key, val, lens, bih2, bhh2, Wout, bout, out);
}

// round 17
// speedup vs baseline: 1.6679x; 1.0195x over previous
#include <cuda_runtime.h>

#define TT  1024
#define NB  128
#define VV  35
#define HH  512
#define VS  128
#define KSZ 128
#define G1  2048
#define ML  250
#define NBLK 128

typedef unsigned long long ull;

__device__ float d_inpc[NB*G1];
__device__ float d_toktab[VV*G1];
__device__ float d_h1[2][NB*HH];
__device__ float d_c1[NB*HH];
__device__ float d_h2[2][NB*KSZ];
__device__ float d_c2[NB*KSZ];
__device__ int   d_tok[NB];
__device__ unsigned d_tokcnt;
__device__ unsigned d_cnt1[4], d_cnt2[4];
__device__ unsigned d_pflag[NB*2];
__device__ float  d_W1t[32*512*64];
__device__ float4 d_W2d[32*640*8];
__device__ int    d_srt[NB];
__device__ int    d_half[NB];
__device__ float  d_pm[NB*2], d_ps[NB*2];
__device__ float  d_pctx[NB*2*VS];

__device__ __forceinline__ ull pack2(float x) {
    unsigned r = __float_as_uint(x); ull d;
    asm("mov.b64 %0, {%1, %2};" : "=l"(d) : "r"(r), "r"(r));
    return d;
}
__device__ __forceinline__ void ffma2(ull& c, ull a, ull b) {
    asm("fma.rn.f32x2 %0, %1, %2, %0;" : "+l"(c) : "l"(a), "l"(b));
}
__device__ __forceinline__ float2 unpack2(ull v) {
    unsigned lo, hi;
    asm("mov.b64 {%0, %1}, %2;" : "=r"(lo), "=r"(hi) : "l"(v));
    return make_float2(__uint_as_float(lo), __uint_as_float(hi));
}
__device__ __forceinline__ float sigf(float x) { return 1.0f / (1.0f + expf(-x)); }
__device__ __forceinline__ void spinge(volatile unsigned* p, unsigned tgt) {
    while (*p < tgt) { }
}
__device__ __forceinline__ void barg(int id) {
    asm volatile("bar.sync %0, 256;" :: "r"(id) : "memory");
}

__global__ void __launch_bounds__(256) k_pre(const float* __restrict__ val,
        const float* __restrict__ emb, const float* __restrict__ Wih1,
        const float* __restrict__ bih1, const float* __restrict__ bhh1,
        const float* __restrict__ Whh1, const float* __restrict__ Wih2,
        const float* __restrict__ Whh2, const int* __restrict__ lens) {
    __shared__ float vp[2][VS];
    __shared__ float vm[VS];
    __shared__ float e[HH];
    int n = blockIdx.x, tid = threadIdx.x;
    {
        int ch = tid & 127, hp = tid >> 7;
        const float* p = val + (size_t)hp*NB*VS + n*VS + ch;
        float s = 0.f;
        #pragma unroll 8
        for (int t = 0; t < TT/2; t++) s += p[(size_t)t*2*NB*VS];
        vp[hp][ch] = s;
    }
    __syncthreads();
    if (tid < VS) vm[tid] = (vp[0][tid] + vp[1][tid]) * (1.0f/TT);
    __syncthreads();
    for (int j = tid; j < G1; j += 256) {
        const float4* w4 = (const float4*)(Wih1 + (size_t)j*(HH+VS) + HH);
        float s = 0.f;
        #pragma unroll 8
        for (int v = 0; v < VS/4; v++) {
            float4 w = w4[v];
            s += w.x*vm[4*v] + w.y*vm[4*v+1] + w.z*vm[4*v+2] + w.w*vm[4*v+3];
        }
        d_inpc[n*G1 + j] = s + bih1[j] + bhh1[j];
    }
    if (n < VV) {
        for (int k = tid; k < HH; k += 256) e[k] = emb[n*HH + k];
        __syncthreads();
        for (int j = tid; j < G1; j += 256) {
            const float4* w4 = (const float4*)(Wih1 + (size_t)j*(HH+VS));
            float s = 0.f;
            #pragma unroll 8
            for (int k = 0; k < HH/4; k++) {
                float4 w = w4[k];
                s += w.x*e[4*k] + w.y*e[4*k+1] + w.z*e[4*k+2] + w.w*e[4*k+3];
            }
            d_toktab[n*G1 + j] = s;
        }
    }
    int mt = n & 31, kq = n >> 5;
    for (int idx = tid; idx < 128*64; idx += 256) {
        int kk = kq*128 + (idx >> 6), c = idx & 63;
        int r = (c >> 4)*HH + mt*16 + (c & 15);
        d_W1t[((size_t)mt*512 + kk)*64 + c] = Whh1[(size_t)r*HH + kk];
    }
    for (int idx = tid; idx < 160*8; idx += 256) {
        int kk = kq*160 + (idx >> 3), c2 = idx & 7;
        int j0 = 2*c2, j1 = j0 + 1;
        int r0 = (j0 >> 2)*KSZ + mt*4 + (j0 & 3);
        int r1 = (j1 >> 2)*KSZ + mt*4 + (j1 & 3);
        float w0 = (kk < 512) ? Wih2[(size_t)r0*HH + kk] : Whh2[(size_t)r0*KSZ + kk - 512];
        float w1 = (kk < 512) ? Wih2[(size_t)r1*HH + kk] : Whh2[(size_t)r1*KSZ + kk - 512];
        d_W2d[((size_t)mt*640 + kk)*8 + c2] = make_float4(w0, w0, w1, w1);
    }
    for (int i = tid; i < HH; i += 256) { d_h1[0][n*HH+i] = 0.f; d_c1[n*HH+i] = 0.f; }
    if (tid < KSZ) { d_h2[0][n*KSZ+tid] = 0.f; d_c2[n*KSZ+tid] = 0.f; }
    if (tid < 2) d_pflag[n*2 + tid] = 0;
    if (tid == 0) {
        d_tok[n] = 0;
        int L = lens[n];
        int h = (((L + 1) >> 1) + 15) & ~15;
        d_half[n] = (h > L) ? L : h;
    }
    if (n == 0 && tid == 0) {
        d_tokcnt = 0;
        for (int i = 0; i < 4; i++) { d_cnt1[i] = 0; d_cnt2[i] = 0; }
        int ord[NB];
        for (int i = 0; i < NB; i++) ord[i] = i;
        for (int i = 0; i < NB-1; i++) {
            int bi = i;
            for (int j = i+1; j < NB; j++)
                if (lens[ord[j]] > lens[ord[bi]]) bi = j;
            int tmp = ord[i]; ord[i] = ord[bi]; ord[bi] = tmp;
        }
        for (int i = 0; i < NB; i++) d_srt[i] = ord[i];
    }
}

struct SMem {
    float Ws[512][64];
    union {
        float As1[512][34];
        float gt1[4][64][33];
        float As2[640][34];
        struct { float gt[8][16][33]; float rs[16][33]; } l2b;
        struct { float h2s[2][KSZ]; float ev[2][528]; float cpart[2][8][VS];
                 float red[2][8], red2[2][8]; } at2;
        struct { float h2s[KSZ]; float ctxs[VS]; float preds[VV]; float cmb[4]; } at;
    } u;
};

// one attention unit handled by a 256-thread group (grp=0 warps 0-7, grp=1 warps 8-15)
__device__ void attn_unit(SMem* sm, const float* __restrict__ key,
        const float* __restrict__ val, const float* __restrict__ h2row,
        int n, int ci, int t0, int tl, int step, int grp) {
    const int gt = threadIdx.x & 255, lane = gt & 31, gwid = gt >> 5;   // 8 warps
    const int bb = grp + 1;
    float* ev  = sm->u.at2.ev[grp];
    float* h2s = sm->u.at2.h2s[grp];
    float* red  = sm->u.at2.red[grp];
    float* red2 = sm->u.at2.red2[grp];
    if (gt < KSZ) h2s[gt] = __ldcg(&h2row[gt]);
    barg(bb);
    const float* krow = key + (size_t)t0*(NB*KSZ) + (size_t)n*KSZ + lane*4;
    const float* vrow = val + (size_t)t0*(NB*VS)  + (size_t)n*VS  + lane*4;
    float4 hv = *(const float4*)&h2s[lane*4];
    float wmax = -3.0e38f;
    int t = gwid;
    for (; t + 24 < tl; t += 32) {
        float4 k0 = *(const float4*)(krow + (size_t)(t     )*(NB*KSZ));
        float4 k1 = *(const float4*)(krow + (size_t)(t +  8)*(NB*KSZ));
        float4 k2 = *(const float4*)(krow + (size_t)(t + 16)*(NB*KSZ));
        float4 k3 = *(const float4*)(krow + (size_t)(t + 24)*(NB*KSZ));
        float s0 = k0.x*hv.x + k0.y*hv.y + k0.z*hv.z + k0.w*hv.w;
        float s1 = k1.x*hv.x + k1.y*hv.y + k1.z*hv.z + k1.w*hv.w;
        float s2 = k2.x*hv.x + k2.y*hv.y + k2.z*hv.z + k2.w*hv.w;
        float s3 = k3.x*hv.x + k3.y*hv.y + k3.z*hv.z + k3.w*hv.w;
        #pragma unroll
        for (int sh = 16; sh; sh >>= 1) {
            s0 += __shfl_xor_sync(~0u, s0, sh); s1 += __shfl_xor_sync(~0u, s1, sh);
            s2 += __shfl_xor_sync(~0u, s2, sh); s3 += __shfl_xor_sync(~0u, s3, sh);
        }
        if (lane == 0) { ev[t]=s0; ev[t+8]=s1; ev[t+16]=s2; ev[t+24]=s3; }
        wmax = fmaxf(wmax, fmaxf(fmaxf(s0,s1), fmaxf(s2,s3)));
    }
    for (; t < tl; t += 8) {
        float4 k0 = *(const float4*)(krow + (size_t)t*(NB*KSZ));
        float s0 = k0.x*hv.x + k0.y*hv.y + k0.z*hv.z + k0.w*hv.w;
        #pragma unroll
        for (int sh = 16; sh; sh >>= 1) s0 += __shfl_xor_sync(~0u, s0, sh);
        if (lane == 0) ev[t] = s0;
        wmax = fmaxf(wmax, s0);
    }
    if (lane == 0) red[gwid] = wmax;
    barg(bb);
    float m = red[0];
    #pragma unroll
    for (int w = 1; w < 8; w++) m = fmaxf(m, red[w]);
    float psum = 0.f;
    for (int q = gt; q < tl; q += 256) { float w = expf(ev[q] - m); ev[q] = w; psum += w; }
    #pragma unroll
    for (int sh = 16; sh; sh >>= 1) psum += __shfl_xor_sync(~0u, psum, sh);
    if (lane == 0) red2[gwid] = psum;
    barg(bb);
    float4 a0 = {0,0,0,0}, a1 = {0,0,0,0};
    t = gwid;
    for (; t + 8 < tl; t += 16) {
        float e0 = ev[t], e1 = ev[t+8];
        float4 v0 = *(const float4*)(vrow + (size_t)(t    )*(NB*VS));
        float4 v1 = *(const float4*)(vrow + (size_t)(t + 8)*(NB*VS));
        a0.x += e0*v0.x; a0.y += e0*v0.y; a0.z += e0*v0.z; a0.w += e0*v0.w;
        a1.x += e1*v1.x; a1.y += e1*v1.y; a1.z += e1*v1.z; a1.w += e1*v1.w;
    }
    for (; t < tl; t += 8) {
        float e0 = ev[t];
        float4 v0 = *(const float4*)(vrow + (size_t)t*(NB*VS));
        a0.x += e0*v0.x; a0.y += e0*v0.y; a0.z += e0*v0.z; a0.w += e0*v0.w;
    }
    a0.x += a1.x; a0.y += a1.y; a0.z += a1.z; a0.w += a1.w;
    *(float4*)&sm->u.at2.cpart[grp][gwid][lane*4] = a0;
    barg(bb);
    if (gt < VS) {
        float s = 0.f;
        #pragma unroll
        for (int w = 0; w < 8; w++) s += sm->u.at2.cpart[grp][w][gt];
        d_pctx[((size_t)n*2 + ci)*VS + gt] = s;
    }
    if (gt == 0) {
        float st = 0.f;
        #pragma unroll
        for (int w = 0; w < 8; w++) st += red2[w];
        d_pm[n*2 + ci] = m;
        d_ps[n*2 + ci] = st;
    }
    __threadfence();
    barg(bb);
    if (gt == 0) *(volatile unsigned*)&d_pflag[n*2 + ci] = (unsigned)(step + 1);
}

__device__ void combine_proj(SMem* sm, const float* __restrict__ Wout,
        const float* __restrict__ bout, float* __restrict__ out,
        const float* __restrict__ h2base, int n, int outstep) {
    const int tid = threadIdx.x, lane = tid & 31, wid = tid >> 5;
    if (tid == 0) {
        unsigned tgt = (unsigned)(outstep + 1);
        spinge(&d_pflag[2*n], tgt);
        spinge(&d_pflag[2*n+1], tgt);
    }
    __syncthreads();
    if (tid < KSZ) sm->u.at.h2s[tid] = __ldcg(&h2base[(size_t)n*KSZ + tid]);
    if (tid == 0) {
        float m0 = __ldcg(&d_pm[2*n]),   m1 = __ldcg(&d_pm[2*n+1]);
        float s0 = __ldcg(&d_ps[2*n]),   s1 = __ldcg(&d_ps[2*n+1]);
        float M = fmaxf(m0, m1);
        float f0 = expf(m0 - M), f1 = expf(m1 - M);
        float S = f0*s0 + f1*s1;
        sm->u.at.cmb[0] = f0; sm->u.at.cmb[1] = f1; sm->u.at.cmb[2] = 1.0f / S;
    }
    __syncthreads();
    if (tid < VS) {
        float c0 = __ldcg(&d_pctx[(size_t)(2*n)*VS + tid]);
        float c1 = __ldcg(&d_pctx[(size_t)(2*n+1)*VS + tid]);
        sm->u.at.ctxs[tid] = (sm->u.at.cmb[0]*c0 + sm->u.at.cmb[1]*c1) * sm->u.at.cmb[2];
    }
    __syncthreads();
    for (int v = wid; v < VV; v += 16) {
        const float* wr = Wout + (size_t)v*(KSZ+VS);
        float s = 0.f;
        #pragma unroll
        for (int kk = 0; kk < 8; kk++) {
            int k = lane + kk*32;
            float x = (k < KSZ) ? sm->u.at.h2s[k] : sm->u.at.ctxs[k-KSZ];
            s += x * wr[k];
        }
        #pragma unroll
        for (int sh = 16; sh; sh >>= 1) s += __shfl_xor_sync(~0u, s, sh);
        if (lane == 0) sm->u.at.preds[v] = s + bout[v];
    }
    __syncthreads();
    if (tid < VV) out[(size_t)n*ML*VV + (size_t)outstep*VV + tid] = sm->u.at.preds[tid];
    if (tid == 0) {
        float best = sm->u.at.preds[0]; int bi = 0;
        #pragma unroll
        for (int v = 1; v < VV; v++)
            if (sm->u.at.preds[v] > best) { best = sm->u.at.preds[v]; bi = v; }
        d_tok[n] = bi;
    }
}

__global__ void __launch_bounds__(512, 1) k_decode(
    const float* __restrict__ key, const float* __restrict__ val,
    const int* __restrict__ lens,
    const float* __restrict__ bih2, const float* __restrict__ bhh2,
    const float* __restrict__ Wout, const float* __restrict__ bout,
    float* __restrict__ out)
{
    extern __shared__ __align__(16) char smraw[];
    SMem* sm = (SMem*)smraw;
    const int bid = blockIdx.x, tid = threadIdx.x;
    const int mt = bid & 31, n0 = (bid >> 5) * 32, nt = bid >> 5;
    const int rowA = d_srt[bid], rowB = d_srt[NBLK-1-bid];
    const int hA = d_half[rowA];
    const int hB = d_half[rowB], LB = lens[rowB];
    const int ntA = rowA >> 5, ntB = rowB >> 5;

    {
        const float4* src = (const float4*)(d_W1t + (size_t)mt*512*64);
        float4* dst = (float4*)sm->Ws;
        for (int i = tid; i < 512*64/4; i += 512) dst[i] = src[i];
    }
    __syncthreads();

    for (int step = 0; step < ML; step++) {
        const int p = step & 1;

        // ===== phase 1: combine(prev) -> tok arrive -> LSTM1 MMA -> tok wait -> epilogue =====
        {
            if (step > 0)
                combine_proj(sm, Wout, bout, out, d_h2[p], bid, step - 1);
            __threadfence();
            if (tid == 0) atomicAdd(&d_tokcnt, 1u);
            __syncthreads();

            const float* h1in = d_h1[p];
            {
                int an = tid & 31, kb = tid >> 5;
                const float* src = h1in + (size_t)(n0 + an)*HH + kb*32;
                #pragma unroll
                for (int q = 0; q < 8; q++) {
                    float4 v = __ldcg((const float4*)(src + q*4));
                    int kk = kb*32 + q*4;
                    sm->u.As1[kk][an] = v.x; sm->u.As1[kk+1][an] = v.y;
                    sm->u.As1[kk+2][an] = v.z; sm->u.As1[kk+3][an] = v.w;
                }
            }
            __syncthreads();
            const int g = tid >> 7, t = tid & 127;
            const int np = t & 7, c4 = t >> 3;
            ull acc[8] = {0,0,0,0,0,0,0,0};
            #pragma unroll 4
            for (int k = 0; k < 128; k++) {
                const float* ar = &sm->u.As1[g*128 + k][np*4];
                ull a0 = *(const ull*)ar, a1 = *(const ull*)(ar + 2);
                float4 w = *(const float4*)&sm->Ws[g*128 + k][c4*4];
                ull b0 = pack2(w.x), b1 = pack2(w.y), b2 = pack2(w.z), b3 = pack2(w.w);
                ffma2(acc[0],a0,b0); ffma2(acc[1],a1,b0);
                ffma2(acc[2],a0,b1); ffma2(acc[3],a1,b1);
                ffma2(acc[4],a0,b2); ffma2(acc[5],a1,b2);
                ffma2(acc[6],a0,b3); ffma2(acc[7],a1,b3);
            }
            __syncthreads();
            #pragma unroll
            for (int j = 0; j < 4; j++) {
                float2 v0 = unpack2(acc[2*j]), v1 = unpack2(acc[2*j+1]);
                float* gr = sm->u.gt1[g][c4*4 + j];
                gr[np*4] = v0.x; gr[np*4+1] = v0.y; gr[np*4+2] = v1.x; gr[np*4+3] = v1.y;
            }
            __syncthreads();
            // tok-independent part before the wait
            int nl = tid >> 4, mi = tid & 15;
            int gn = n0 + nl, gm = mt*16 + mi;
            const float* ic = d_inpc + (size_t)gn*G1;
            float base[4];
            #pragma unroll
            for (int gg = 0; gg < 4; gg++) {
                int col = gg*16 + mi;
                base[gg] = sm->u.gt1[0][col][nl] + sm->u.gt1[1][col][nl]
                         + sm->u.gt1[2][col][nl] + sm->u.gt1[3][col][nl]
                         + ic[gg*HH + gm];
            }
            float cp = d_c1[gn*HH + gm];
            if (tid == 0) spinge(&d_tokcnt, (unsigned)(NBLK * (step + 1)));
            __syncthreads();
            int tk = __ldcg(&d_tok[gn]);
            const float* tt = d_toktab + (size_t)tk*G1;
            float g4[4];
            #pragma unroll
            for (int gg = 0; gg < 4; gg++) g4[gg] = base[gg] + tt[gg*HH + gm];
            float cn = sigf(g4[1])*cp + sigf(g4[0])*tanhf(g4[2]);
            d_c1[gn*HH + gm] = cn;
            d_h1[p^1][gn*HH + gm] = sigf(g4[3])*tanhf(cn);
            __threadfence();
            __syncthreads();
            if (tid == 0) atomicAdd(&d_cnt1[nt], 1u);
        }

        // ===== LSTM2 =====
        {
            if (tid == 0) {
                spinge(&d_cnt1[nt], (unsigned)(32 * (step + 1)));
                if (step > 0) spinge(&d_cnt2[nt], (unsigned)(32 * step));
            }
            __syncthreads();
            const float* h1n = d_h1[p^1];
            const float* h2p = d_h2[p];
            {
                int an = tid & 31, kb = tid >> 5;
                #pragma unroll
                for (int q = 0; q < 10; q++) {
                    int kk = kb*40 + q*4;
                    float4 v = (kk < 512)
                        ? __ldcg((const float4*)(h1n + (size_t)(n0 + an)*HH  + kk))
                        : __ldcg((const float4*)(h2p + (size_t)(n0 + an)*KSZ + kk - 512));
                    sm->u.As2[kk][an] = v.x; sm->u.As2[kk+1][an] = v.y;
                    sm->u.As2[kk+2][an] = v.z; sm->u.As2[kk+3][an] = v.w;
                }
            }
            __syncthreads();
            const int g2 = tid >> 6, t2 = tid & 63;
            const int np = t2 & 7, c2 = t2 >> 3;
            const int kb2 = g2 * 80;
            const ulonglong2* bp = (const ulonglong2*)d_W2d + ((size_t)mt*640 + kb2)*8 + c2;
            ull A00=0, A01=0, A10=0, A11=0;
            #pragma unroll 8
            for (int k = 0; k < 80; k++) {
                const float* ar = &sm->u.As2[kb2 + k][np*4];
                ull a0 = *(const ull*)ar, a1 = *(const ull*)(ar + 2);
                ulonglong2 b = bp[(size_t)k*8];
                ffma2(A00, a0, b.x); ffma2(A10, a1, b.x);
                ffma2(A01, a0, b.y); ffma2(A11, a1, b.y);
            }
            __syncthreads();
            { float2 v;
              v = unpack2(A00); sm->u.l2b.gt[g2][2*c2  ][np*4  ] = v.x; sm->u.l2b.gt[g2][2*c2  ][np*4+1] = v.y;
              v = unpack2(A10); sm->u.l2b.gt[g2][2*c2  ][np*4+2] = v.x; sm->u.l2b.gt[g2][2*c2  ][np*4+3] = v.y;
              v = unpack2(A01); sm->u.l2b.gt[g2][2*c2+1][np*4  ] = v.x; sm->u.l2b.gt[g2][2*c2+1][np*4+1] = v.y;
              v = unpack2(A11); sm->u.l2b.gt[g2][2*c2+1][np*4+2] = v.x; sm->u.l2b.gt[g2][2*c2+1][np*4+3] = v.y; }
            __syncthreads();
            {
                int cc = tid & 15, nl = tid >> 4;
                float s = 0.f;
                #pragma unroll
                for (int w = 0; w < 8; w++) s += sm->u.l2b.gt[w][cc][nl];
                sm->u.l2b.rs[cc][nl] = s;
            }
            __syncthreads();
            if (tid < 128) {
                int nl = tid >> 2, ci = tid & 3;
                int gn = n0 + nl, gm = mt*4 + ci;
                float g4[4];
                #pragma unroll
                for (int gg = 0; gg < 4; gg++) {
                    int r = gg*KSZ + gm;
                    g4[gg] = sm->u.l2b.rs[gg*4 + ci][nl] + bih2[r] + bhh2[r];
                }
                float cp = d_c2[gn*KSZ + gm];
                float cn = sigf(g4[1])*cp + sigf(g4[0])*tanhf(g4[2]);
                d_c2[gn*KSZ + gm] = cn;
                d_h2[p^1][gn*KSZ + gm] = sigf(g4[3])*tanhf(cn);
            }
            __threadfence();
            __syncthreads();
            if (tid == 0) atomicAdd(&d_cnt2[nt], 1u);
        }

        // ===== attention: two units concurrently (warp-specialized groups) =====
        {
            const int grp = tid >> 8;
            const int gt = tid & 255;
            int n  = grp ? rowB : rowA;
            int t0 = grp ? hB : 0;
            int tl = grp ? (LB - hB) : hA;
            int ntX = grp ? ntB : ntA;
            if (gt == 0) spinge(&d_cnt2[ntX], (unsigned)(32 * (step + 1)));
            barg(grp + 1);
            attn_unit(sm, key, val, d_h2[p^1] + (size_t)n*KSZ, n, grp, t0, tl, step, grp);
        }
    }

    combine_proj(sm, Wout, bout, out, d_h2[ML & 1], bid, ML - 1);
}

extern "C" void kernel_launch(void* const* d_in, const int* in_sizes, int n_in,
                              void* d_out, int out_size) {
    const float* key  = (const float*)d_in[0];
    const float* val  = (const float*)d_in[1];
    const int*   lens = (const int*)  d_in[2];
    const float* emb  = (const float*)d_in[3];
    const float* Wih1 = (const float*)d_in[4];
    const float* Whh1 = (const float*)d_in[5];
    const float* bih1 = (const float*)d_in[6];
    const float* bhh1 = (const float*)d_in[7];
    const float* Wih2 = (const float*)d_in[8];
    const float* Whh2 = (const float*)d_in[9];
    const float* bih2 = (const float*)d_in[10];
    const float* bhh2 = (const float*)d_in[11];
    const float* Wout = (const float*)d_in[12];
    const float* bout = (const float*)d_in[13];
    float* out = (float*)d_out;

    cudaFuncSetAttribute(k_decode, cudaFuncAttributeMaxDynamicSharedMemorySize,
                         (int)sizeof(SMem));
    k_pre<<<NB, 256>>>(val, emb, Wih1, bih1, bhh1, Whh1, Wih2, Whh2, lens);
    k_decode<<<NBLK, 512, sizeof(SMem)>>>(key, val, lens, bih2, bhh2, Wout, bout, out);
}